// round 14
// baseline (speedup 1.0000x reference)
#include <cuda_runtime.h>
#include <cuda_fp16.h>
#include <stdint.h>
#include <math.h>

#define T_TOK 4096
#define DIM   2048
#define INTER 1024
#define NEXP  8
#define NE    9      // 8 routed + 1 shared pseudo-expert

// ---------------- scratch (device globals; no allocation allowed) ----------------
__device__ __half g_hidden [(size_t)NE * T_TOK * INTER];  // post-SwiGLU hidden (fp16)
__device__ __half g_pairout[(size_t)NE * T_TOK * DIM];    // weighted expert outputs (fp16)
__device__ __half g_xh     [(size_t)T_TOK * DIM];         // fp16 activations
__device__ __half g_w1h [(size_t)NEXP * INTER * DIM];
__device__ __half g_w3h [(size_t)NEXP * INTER * DIM];
__device__ __half g_w2h [(size_t)NEXP * DIM * INTER];
__device__ __half g_ws1h[(size_t)INTER * DIM];
__device__ __half g_ws3h[(size_t)INTER * DIM];
__device__ __half g_ws2h[(size_t)DIM * INTER];
__device__ int    g_pair_tok[NE * T_TOK];
__device__ float  g_pair_w [NE * T_TOK];
__device__ int    g_tok_rows[T_TOK * 2];
__device__ int    g_cnt[NE];

// ---------------- PTX helpers ----------------
__device__ __forceinline__ uint32_t smem_u32(const void* p) {
    return (uint32_t)__cvta_generic_to_shared(p);
}
__device__ __forceinline__ void cp16(uint32_t dst, const void* src, bool valid) {
    int sz = valid ? 16 : 0;
    asm volatile("cp.async.cg.shared.global [%0], [%1], 16, %2;\n"
                 :: "r"(dst), "l"(src), "r"(sz));
}
#define CP_COMMIT() asm volatile("cp.async.commit_group;\n")
#define CP_WAIT1()  asm volatile("cp.async.wait_group 1;\n")
#define CP_WAIT0()  asm volatile("cp.async.wait_group 0;\n")

#define LDSM4(r0, r1, r2, r3, a) \
    asm volatile("ldmatrix.sync.aligned.m8n8.x4.shared.b16 {%0,%1,%2,%3}, [%4];" \
                 : "=r"(r0), "=r"(r1), "=r"(r2), "=r"(r3) : "r"(a))

#define MMA16816(c, a, b) \
    asm volatile("mma.sync.aligned.m16n8k16.row.col.f32.f16.f16.f32 " \
                 "{%0,%1,%2,%3},{%4,%5,%6,%7},{%8,%9},{%0,%1,%2,%3};" \
                 : "+f"((c)[0]), "+f"((c)[1]), "+f"((c)[2]), "+f"((c)[3]) \
                 : "r"((a)[0]), "r"((a)[1]), "r"((a)[2]), "r"((a)[3]), \
                   "r"((b)[0]), "r"((b)[1]))

// SW128 swizzle for 128B rows: 16B chunk index XOR row%8 -> conflict-free LDSM + cp.async
__device__ __forceinline__ uint32_t swz(uint32_t row, uint32_t c) {
    return row * 128 + ((c ^ (row & 7)) << 4);
}

// ---------------- kernel 0: reset counters (must precede gate atomics) ----------
__global__ void init_kernel() {
    int i = threadIdx.x;
    if (i < NE) g_cnt[i] = (i == NEXP) ? T_TOK : 0;
}

// ---------------- fused gate + weight-convert ----------------
// blocks [0, T_TOK):        gate for token blockIdx.x (+ fp16 x copy)
// blocks [T_TOK, T_TOK+CVB): grid-stride convert over 6 segments
struct Seg { const float4* src; uint2* dst; int n4; };
#define CVB 2048

__global__ void prep_kernel(const float* __restrict__ x,
                            const float* __restrict__ gw,
                            Seg s0, Seg s1, Seg s2, Seg s3, Seg s4, Seg s5) {
    if (blockIdx.x >= T_TOK) {
        // ---- convert part ----
        Seg segs[6] = { s0, s1, s2, s3, s4, s5 };
        int stride = CVB * blockDim.x;
        int tid = (blockIdx.x - T_TOK) * blockDim.x + threadIdx.x;
#pragma unroll
        for (int s = 0; s < 6; s++) {
            const float4* src = segs[s].src;
            uint2* dst = segs[s].dst;
            int n4 = segs[s].n4;
            for (int i = tid; i < n4; i += stride) {
                float4 v = src[i];
                __half2 a = __floats2half2_rn(v.x, v.y);
                __half2 b = __floats2half2_rn(v.z, v.w);
                uint2 o;
                o.x = *(uint32_t*)&a;
                o.y = *(uint32_t*)&b;
                dst[i] = o;
            }
        }
        return;
    }
    // ---- gate part ----
    int t = blockIdx.x;
    const float* xr = x + (size_t)t * DIM;
    __half* xo = g_xh + (size_t)t * DIM;

    float acc[NEXP];
#pragma unroll
    for (int e = 0; e < NEXP; e++) acc[e] = 0.f;
    for (int d = threadIdx.x; d < DIM; d += 256) {
        float xv = xr[d];
        xo[d] = __float2half_rn(xv);
#pragma unroll
        for (int e = 0; e < NEXP; e++) acc[e] += xv * gw[e * DIM + d];
    }
#pragma unroll
    for (int off = 16; off > 0; off >>= 1) {
#pragma unroll
        for (int e = 0; e < NEXP; e++)
            acc[e] += __shfl_down_sync(0xffffffffu, acc[e], off);
    }
    __shared__ float sw[8][NEXP];
    int warp = threadIdx.x >> 5, lane = threadIdx.x & 31;
    if (lane == 0) {
#pragma unroll
        for (int e = 0; e < NEXP; e++) sw[warp][e] = acc[e];
    }
    __syncthreads();
    if (threadIdx.x == 0) {
        float lg[NEXP];
#pragma unroll
        for (int e = 0; e < NEXP; e++) {
            float s = 0.f;
#pragma unroll
            for (int w = 0; w < 8; w++) s += sw[w][e];
            lg[e] = s;
        }
        float mx = lg[0];
#pragma unroll
        for (int e = 1; e < NEXP; e++) mx = fmaxf(mx, lg[e]);
        float p[NEXP]; float sum = 0.f;
#pragma unroll
        for (int e = 0; e < NEXP; e++) { p[e] = expf(lg[e] - mx); sum += p[e]; }
        float inv = 1.f / sum;
#pragma unroll
        for (int e = 0; e < NEXP; e++) p[e] *= inv;
        int i1 = 0;
#pragma unroll
        for (int e = 1; e < NEXP; e++) if (p[e] > p[i1]) i1 = e;
        int i2 = (i1 == 0) ? 1 : 0;
#pragma unroll
        for (int e = 0; e < NEXP; e++) if (e != i1 && p[e] > p[i2]) i2 = e;

        int s1 = atomicAdd(&g_cnt[i1], 1);
        g_pair_tok[i1 * T_TOK + s1] = t;
        g_pair_w [i1 * T_TOK + s1] = p[i1];
        int s2 = atomicAdd(&g_cnt[i2], 1);
        g_pair_tok[i2 * T_TOK + s2] = t;
        g_pair_w [i2 * T_TOK + s2] = p[i2];
        g_tok_rows[2 * t]     = i1 * T_TOK + s1;
        g_tok_rows[2 * t + 1] = i2 * T_TOK + s2;
        g_pair_tok[NEXP * T_TOK + t] = t;
        g_pair_w [NEXP * T_TOK + t] = 1.0f;
    }
}

// ================= fp16 up-proj: H = silu(X W1^T) * (X W3^T) =================
// CTA tile M=128, N=64 dual-matrix. BK=64 (128B SW128 rows), 3-stage x 32KB.
// Iteration order: barrier -> LDSM ks0 -> issue prefetch -> ks loop.
#define UPSTG 32768

__global__ __launch_bounds__(256, 2)
void up_kernel() {
    extern __shared__ __align__(1024) char dsm[];

    int e = blockIdx.z;
    int cnt = g_cnt[e];
    int m0 = blockIdx.y * 128;
    if (m0 >= cnt) return;
    int n0 = blockIdx.x * 64;

    const __half* B1 = (e < NEXP) ? g_w1h + (size_t)e * INTER * DIM : g_ws1h;
    const __half* B3 = (e < NEXP) ? g_w3h + (size_t)e * INTER * DIM : g_ws3h;

    int tid = threadIdx.x;
    int wid = tid >> 5, lane = tid & 31;
    uint32_t tb = smem_u32(dsm);

    uint32_t aoff[4]; const __half* asrc[4]; bool aval[4];
#pragma unroll
    for (int j = 0; j < 4; j++) {
        int idx = tid + j * 256;
        int row = idx >> 3, c = idx & 7;
        aoff[j] = swz(row, c);
        int r = m0 + row;
        aval[j] = (r < cnt);
        int tok = aval[j] ? g_pair_tok[e * T_TOK + r] : 0;
        asrc[j] = g_xh + (size_t)tok * DIM + c * 8;
    }
    uint32_t boff[2]; const __half *b1src[2], *b3src[2];
#pragma unroll
    for (int j = 0; j < 2; j++) {
        int idx = tid + j * 256;
        int row = idx >> 3, c = idx & 7;
        boff[j] = swz(row, c);
        b1src[j] = B1 + (size_t)(n0 + row) * DIM + c * 8;
        b3src[j] = B3 + (size_t)(n0 + row) * DIM + c * 8;
    }

    int wm = (wid & 1) * 64, wn = (wid >> 1) * 16;
    int lr = lane & 15, lc = lane >> 4;
    int g = lane >> 2, tg = lane & 3;

    int rA[4], rB;
#pragma unroll
    for (int mi = 0; mi < 4; mi++) rA[mi] = wm + mi * 16 + lr;
    rB = wn + lr;

    float acc1[4][2][4], acc3[4][2][4];
#pragma unroll
    for (int mi = 0; mi < 4; mi++)
#pragma unroll
        for (int ni = 0; ni < 2; ni++)
#pragma unroll
            for (int q = 0; q < 4; q++) { acc1[mi][ni][q] = 0.f; acc3[mi][ni][q] = 0.f; }

    const int NIT = DIM / 64;   // 32
#pragma unroll
    for (int st = 0; st < 2; st++) {
        uint32_t sb = tb + st * UPSTG;
#pragma unroll
        for (int j = 0; j < 4; j++) cp16(sb + aoff[j], asrc[j] + st * 64, aval[j]);
#pragma unroll
        for (int j = 0; j < 2; j++) {
            cp16(sb + 16384 + boff[j], b1src[j] + st * 64, true);
            cp16(sb + 24576 + boff[j], b3src[j] + st * 64, true);
        }
        CP_COMMIT();
    }

    uint32_t af[2][4][4], b1f[2][2][2], b3f[2][2][2];

    auto iter = [&](int it, uint32_t sb, uint32_t psb) {
        if (it < NIT - 1) CP_WAIT1(); else CP_WAIT0();
        __syncthreads();
        // 1) fragments for ks=0 FIRST: unblocks the tensor pipe ASAP
#pragma unroll
        for (int mi = 0; mi < 4; mi++)
            LDSM4(af[0][mi][0], af[0][mi][1], af[0][mi][2], af[0][mi][3],
                  sb + swz(rA[mi], lc));
        {
            uint32_t r0, r1, r2, r3;
            LDSM4(r0, r1, r2, r3, sb + 16384 + swz(rB, lc));
            b1f[0][0][0] = r0; b1f[0][0][1] = r2; b1f[0][1][0] = r1; b1f[0][1][1] = r3;
            LDSM4(r0, r1, r2, r3, sb + 24576 + swz(rB, lc));
            b3f[0][0][0] = r0; b3f[0][0][1] = r2; b3f[0][1][0] = r1; b3f[0][1][1] = r3;
        }
        // 2) prefetch stage it+2 (LSU work overlaps the MMA stream below)
        int pf = it + 2;
        if (pf < NIT) {
#pragma unroll
            for (int j = 0; j < 4; j++) cp16(psb + aoff[j], asrc[j] + pf * 64, aval[j]);
#pragma unroll
            for (int j = 0; j < 2; j++) {
                cp16(psb + 16384 + boff[j], b1src[j] + pf * 64, true);
                cp16(psb + 24576 + boff[j], b3src[j] + pf * 64, true);
            }
            CP_COMMIT();
        }
        // 3) ks loop with register double-buffering
#pragma unroll
        for (int ks = 0; ks < 4; ks++) {
            int cur = ks & 1, nxt = cur ^ 1;
            if (ks < 3) {
                int c = (ks + 1) * 2 + lc;
#pragma unroll
                for (int mi = 0; mi < 4; mi++)
                    LDSM4(af[nxt][mi][0], af[nxt][mi][1], af[nxt][mi][2], af[nxt][mi][3],
                          sb + swz(rA[mi], c));
                uint32_t r0, r1, r2, r3;
                LDSM4(r0, r1, r2, r3, sb + 16384 + swz(rB, c));
                b1f[nxt][0][0] = r0; b1f[nxt][0][1] = r2; b1f[nxt][1][0] = r1; b1f[nxt][1][1] = r3;
                LDSM4(r0, r1, r2, r3, sb + 24576 + swz(rB, c));
                b3f[nxt][0][0] = r0; b3f[nxt][0][1] = r2; b3f[nxt][1][0] = r1; b3f[nxt][1][1] = r3;
            }
#pragma unroll
            for (int mi = 0; mi < 4; mi++)
#pragma unroll
                for (int ni = 0; ni < 2; ni++) {
                    MMA16816(acc1[mi][ni], af[cur][mi], b1f[cur][ni]);
                    MMA16816(acc3[mi][ni], af[cur][mi], b3f[cur][ni]);
                }
        }
    };

    for (int base = 0; base < NIT; base += 3) {
        iter(base,     tb,             tb + 2 * UPSTG);
        if (base + 1 < NIT) iter(base + 1, tb + UPSTG,     tb);
        if (base + 2 < NIT) iter(base + 2, tb + 2 * UPSTG, tb + UPSTG);
    }

    // epilogue: silu(h1)*h3 -> g_hidden (fp16)
#pragma unroll
    for (int mi = 0; mi < 4; mi++)
#pragma unroll
        for (int h = 0; h < 2; h++) {
            int m = wm + mi * 16 + g + h * 8;
            int slot = m0 + m;
            if (slot < cnt) {
                __half* dst = g_hidden + ((size_t)e * T_TOK + slot) * INTER + n0;
#pragma unroll
                for (int ni = 0; ni < 2; ni++) {
                    int n = wn + ni * 8 + 2 * tg;
                    float h1a = acc1[mi][ni][h * 2], h1b = acc1[mi][ni][h * 2 + 1];
                    float h3a = acc3[mi][ni][h * 2], h3b = acc3[mi][ni][h * 2 + 1];
                    float va = (h1a / (1.f + __expf(-h1a))) * h3a;
                    float vb = (h1b / (1.f + __expf(-h1b))) * h3b;
                    *(__half2*)&dst[n] = __floats2half2_rn(va, vb);
                }
            }
        }
}

// ================= fp16 down-proj: O = H W2^T, weight-folded fp16 store =================
#define DNSTG 32768

__global__ __launch_bounds__(256, 2)
void down_kernel() {
    extern __shared__ __align__(1024) char dsm[];

    int e = blockIdx.z;
    int cnt = g_cnt[e];
    int m0 = blockIdx.y * 128;
    if (m0 >= cnt) return;
    int n0 = blockIdx.x * 128;

    const __half* B = (e < NEXP) ? g_w2h + (size_t)e * DIM * INTER : g_ws2h;

    int tid = threadIdx.x;
    int wid = tid >> 5, lane = tid & 31;
    uint32_t tb = smem_u32(dsm);

    uint32_t aoff[4]; const __half* asrc[4]; bool aval[4];
    const __half* bsrc[4];
#pragma unroll
    for (int j = 0; j < 4; j++) {
        int idx = tid + j * 256;
        int row = idx >> 3, c = idx & 7;
        aoff[j] = swz(row, c);
        int r = m0 + row;
        aval[j] = (r < cnt);
        asrc[j] = g_hidden + ((size_t)e * T_TOK + (aval[j] ? r : 0)) * INTER + c * 8;
        bsrc[j] = B + (size_t)(n0 + row) * INTER + c * 8;
    }

    int wm = (wid & 1) * 64, wn = (wid >> 1) * 32;
    int lr = lane & 15, lc = lane >> 4;
    int g = lane >> 2, tg = lane & 3;

    int rA[4], rB[2];
#pragma unroll
    for (int mi = 0; mi < 4; mi++) rA[mi] = wm + mi * 16 + lr;
#pragma unroll
    for (int bi = 0; bi < 2; bi++) rB[bi] = wn + bi * 16 + lr;

    float acc[4][4][4];
#pragma unroll
    for (int mi = 0; mi < 4; mi++)
#pragma unroll
        for (int ni = 0; ni < 4; ni++)
#pragma unroll
            for (int q = 0; q < 4; q++) acc[mi][ni][q] = 0.f;

    const int NIT = INTER / 64;   // 16
#pragma unroll
    for (int st = 0; st < 2; st++) {
        uint32_t sb = tb + st * DNSTG;
#pragma unroll
        for (int j = 0; j < 4; j++) {
            cp16(sb + aoff[j], asrc[j] + st * 64, aval[j]);
            cp16(sb + 16384 + aoff[j], bsrc[j] + st * 64, true);
        }
        CP_COMMIT();
    }

    uint32_t af[2][4][4], bf[2][4][2];

    auto iter = [&](int it, uint32_t sb, uint32_t psb) {
        if (it < NIT - 1) CP_WAIT1(); else CP_WAIT0();
        __syncthreads();
        // 1) ks=0 fragments first
#pragma unroll
        for (int mi = 0; mi < 4; mi++)
            LDSM4(af[0][mi][0], af[0][mi][1], af[0][mi][2], af[0][mi][3],
                  sb + swz(rA[mi], lc));
#pragma unroll
        for (int bi = 0; bi < 2; bi++) {
            uint32_t r0, r1, r2, r3;
            LDSM4(r0, r1, r2, r3, sb + 16384 + swz(rB[bi], lc));
            bf[0][bi * 2][0] = r0; bf[0][bi * 2][1] = r2;
            bf[0][bi * 2 + 1][0] = r1; bf[0][bi * 2 + 1][1] = r3;
        }
        // 2) prefetch stage it+2
        int pf = it + 2;
        if (pf < NIT) {
#pragma unroll
            for (int j = 0; j < 4; j++) {
                cp16(psb + aoff[j], asrc[j] + pf * 64, aval[j]);
                cp16(psb + 16384 + aoff[j], bsrc[j] + pf * 64, true);
            }
            CP_COMMIT();
        }
        // 3) ks loop
#pragma unroll
        for (int ks = 0; ks < 4; ks++) {
            int cur = ks & 1, nxt = cur ^ 1;
            if (ks < 3) {
                int c = (ks + 1) * 2 + lc;
#pragma unroll
                for (int mi = 0; mi < 4; mi++)
                    LDSM4(af[nxt][mi][0], af[nxt][mi][1], af[nxt][mi][2], af[nxt][mi][3],
                          sb + swz(rA[mi], c));
#pragma unroll
                for (int bi = 0; bi < 2; bi++) {
                    uint32_t r0, r1, r2, r3;
                    LDSM4(r0, r1, r2, r3, sb + 16384 + swz(rB[bi], c));
                    bf[nxt][bi * 2][0] = r0; bf[nxt][bi * 2][1] = r2;
                    bf[nxt][bi * 2 + 1][0] = r1; bf[nxt][bi * 2 + 1][1] = r3;
                }
            }
#pragma unroll
            for (int mi = 0; mi < 4; mi++)
#pragma unroll
                for (int ni = 0; ni < 4; ni++)
                    MMA16816(acc[mi][ni], af[cur][mi], bf[cur][ni]);
        }
    };

    for (int base = 0; base < NIT; base += 3) {
        iter(base,     tb,             tb + 2 * DNSTG);
        if (base + 1 < NIT) iter(base + 1, tb + DNSTG,     tb);
        if (base + 2 < NIT) iter(base + 2, tb + 2 * DNSTG, tb + DNSTG);
    }

    // epilogue: weight-fold + fp16 store to pairout
#pragma unroll
    for (int mi = 0; mi < 4; mi++)
#pragma unroll
        for (int h = 0; h < 2; h++) {
            int m = wm + mi * 16 + g + h * 8;
            int slot = m0 + m;
            if (slot < cnt) {
                float wv = g_pair_w[e * T_TOK + slot];
                __half* dst = g_pairout + ((size_t)e * T_TOK + slot) * DIM + n0;
#pragma unroll
                for (int ni = 0; ni < 4; ni++) {
                    int n = wn + ni * 8 + 2 * tg;
                    *(__half2*)&dst[n] = __floats2half2_rn(acc[mi][ni][h * 2] * wv,
                                                           acc[mi][ni][h * 2 + 1] * wv);
                }
            }
        }
}

// ---------------- combine (2 routed rows + shared row, fp16 in / fp32 out) ----------------
__global__ void combine_kernel(float* __restrict__ out) {
    int t = blockIdx.x;
    int r1 = g_tok_rows[2 * t], r2 = g_tok_rows[2 * t + 1];
    const uint2* p1 = (const uint2*)(g_pairout + (size_t)r1 * DIM);
    const uint2* p2 = (const uint2*)(g_pairout + (size_t)r2 * DIM);
    const uint2* ps = (const uint2*)(g_pairout + ((size_t)NEXP * T_TOK + t) * DIM);
    float4* o = (float4*)(out + (size_t)t * DIM);
    for (int i = threadIdx.x; i < DIM / 4; i += 256) {
        uint2 u1 = p1[i], u2 = p2[i], us = ps[i];
        float2 a0 = __half22float2(*(__half2*)&u1.x);
        float2 a1 = __half22float2(*(__half2*)&u1.y);
        float2 b0 = __half22float2(*(__half2*)&u2.x);
        float2 b1 = __half22float2(*(__half2*)&u2.y);
        float2 c0 = __half22float2(*(__half2*)&us.x);
        float2 c1 = __half22float2(*(__half2*)&us.y);
        o[i] = make_float4(a0.x + b0.x + c0.x, a0.y + b0.y + c0.y,
                           a1.x + b1.x + c1.x, a1.y + b1.y + c1.y);
    }
}

// ---------------- launch ----------------
extern "C" void kernel_launch(void* const* d_in, const int* in_sizes, int n_in,
                              void* d_out, int out_size) {
    const float* x      = (const float*)d_in[0];
    const float* gate_w = (const float*)d_in[1];
    const float* w1     = (const float*)d_in[2];
    const float* w2     = (const float*)d_in[3];
    const float* w3     = (const float*)d_in[4];
    const float* ws1    = (const float*)d_in[5];
    const float* ws2    = (const float*)d_in[6];
    const float* ws3    = (const float*)d_in[7];
    float* out = (float*)d_out;

    cudaFuncSetAttribute(up_kernel,   cudaFuncAttributeMaxDynamicSharedMemorySize, 3 * UPSTG);
    cudaFuncSetAttribute(down_kernel, cudaFuncAttributeMaxDynamicSharedMemorySize, 3 * DNSTG);

    __half* w1h;  cudaGetSymbolAddress((void**)&w1h,  g_w1h);
    __half* w3h;  cudaGetSymbolAddress((void**)&w3h,  g_w3h);
    __half* w2h;  cudaGetSymbolAddress((void**)&w2h,  g_w2h);
    __half* ws1h; cudaGetSymbolAddress((void**)&ws1h, g_ws1h);
    __half* ws3h; cudaGetSymbolAddress((void**)&ws3h, g_ws3h);
    __half* ws2h; cudaGetSymbolAddress((void**)&ws2h, g_ws2h);

    Seg s0 = { (const float4*)w1,  (uint2*)w1h,  NEXP * INTER * DIM / 4 };
    Seg s1 = { (const float4*)w3,  (uint2*)w3h,  NEXP * INTER * DIM / 4 };
    Seg s2 = { (const float4*)w2,  (uint2*)w2h,  NEXP * DIM * INTER / 4 };
    Seg s3 = { (const float4*)ws1, (uint2*)ws1h, INTER * DIM / 4 };
    Seg s4 = { (const float4*)ws3, (uint2*)ws3h, DIM * INTER / 4 };
    Seg s5 = { (const float4*)ws2, (uint2*)ws2h, DIM * INTER / 4 };

    init_kernel<<<1, 32>>>();
    prep_kernel<<<T_TOK + CVB, 256>>>(x, gate_w, s0, s1, s2, s3, s4, s5);
    {
        dim3 grid(INTER / 64, T_TOK / 128, NE);
        up_kernel<<<grid, 256, 3 * UPSTG>>>();
    }
    {
        dim3 grid(DIM / 128, T_TOK / 128, NE);
        down_kernel<<<grid, 256, 3 * DNSTG>>>();
    }
    combine_kernel<<<T_TOK, 256>>>(out);
}